// round 7
// baseline (speedup 1.0000x reference)
#include <cuda_runtime.h>
#include <cuda_bf16.h>
#include <cstdint>

#define NN 20000
#define EE 640000
#define DD 64
#define NCHUNK 8
#define CHN (NN / NCHUNK)   // 2500

// ---------------- device scratch ----------------
__device__ float g_h[NN * DD];       // layer-0 features fp32 (dest-side reads)
__device__ float g_h2[NN * DD];      // layer-1 features fp32
__device__ float g_x1[NN * DD];      // relu(edge0 out + b0), input to bmm1
__device__ uint4 g_pack[NN * 16];    // per node: 128B att2 bf16 | 128B h bf16
__device__ uint4 g_pack2[NN * 16];   // same for layer 1
__device__ float g_s1[NN];
__device__ float g_s1b[NN];
__device__ int   g_srow[EE];         // source rows sorted by destination
__device__ int   g_cnt[NN];
__device__ int   g_off[NN + 1];
__device__ int   g_cur[NN];
__device__ int   g_is64;

// ---------------- preprocessing ----------------
__global__ void k_detect_zero(const void* ei) {
    int t = blockIdx.x * blockDim.x + threadIdx.x;
    if (t < NN) g_cnt[t] = 0;
    if (t == 0) {
        // int32 buffer read as int64 pairs two indices: hi word nonzero w.h.p.
        const long long* p = (const long long*)ei;
        int ok = 1;
        for (int k = 0; k < 64; k++) {
            long long v = p[k];
            if (v < 0 || v >= NN) { ok = 0; break; }
        }
        g_is64 = ok;
    }
}

__global__ void k_hist(const void* ei) {
    int e = blockIdx.x * blockDim.x + threadIdx.x;
    if (e >= EE) return;
    int c;
    if (g_is64) c = (int)((const long long*)ei)[EE + e];
    else        c = ((const int*)ei)[EE + e];
    atomicAdd(&g_cnt[c], 1);
}

__global__ void k_scan() {
    __shared__ int sh[1024];
    int t = threadIdx.x;
    const int CH = (NN + 1023) / 1024;  // 20
    int base = t * CH;
    int s = 0;
#pragma unroll
    for (int i = 0; i < CH; i++) {
        int idx = base + i;
        if (idx < NN) s += g_cnt[idx];
    }
    sh[t] = s;
    __syncthreads();
    for (int off = 1; off < 1024; off <<= 1) {
        int v = (t >= off) ? sh[t - off] : 0;
        __syncthreads();
        sh[t] += v;
        __syncthreads();
    }
    int run = sh[t] - s;
    for (int i = 0; i < CH; i++) {
        int idx = base + i;
        if (idx < NN) {
            g_off[idx] = run;
            g_cur[idx] = run;
            run += g_cnt[idx];
        }
    }
    if (t == 1023) g_off[NN] = sh[1023];
}

__global__ void k_scatter(const void* ei) {
    int e = blockIdx.x * blockDim.x + threadIdx.x;
    if (e >= EE) return;
    int r, c;
    if (g_is64) {
        const long long* p = (const long long*)ei;
        r = (int)p[e];
        c = (int)p[EE + e];
    } else {
        const int* p = (const int*)ei;
        r = p[e];
        c = p[EE + e];
    }
    int pos = atomicAdd(&g_cur[c], 1);
    g_srow[pos] = r;
}

// ---------------- helpers ----------------
__device__ __forceinline__ uint2 to_bf16x4(float4 v) {
    __nv_bfloat162 p0 = __float22bfloat162_rn(make_float2(v.x, v.y));
    __nv_bfloat162 p1 = __float22bfloat162_rn(make_float2(v.z, v.w));
    uint2 u;
    u.x = *reinterpret_cast<unsigned*>(&p0);
    u.y = *reinterpret_cast<unsigned*>(&p1);
    return u;
}
__device__ __forceinline__ float2 bf2f(unsigned u) {
    return __bfloat1622float2(*reinterpret_cast<__nv_bfloat162*>(&u));
}

// bmm body: out cols 4sub.. for this node (valid in half==0 lanes).
// w loads use evict-first (.cs): read-once stream, keep pack records L2-resident.
__device__ __forceinline__ float4 bmm_body(const float4* __restrict__ wn4,
                                           const float* xs, int half, int sub) {
    float4 acc = make_float4(0.f, 0.f, 0.f, 0.f);
#pragma unroll
    for (int i = 0; i < 32; i++) {
        int r = half * 32 + i;
        float  xd = xs[r];
        float4 wv = __ldcs(&wn4[r * 16 + sub]);
        acc.x += xd * wv.x;
        acc.y += xd * wv.y;
        acc.z += xd * wv.z;
        acc.w += xd * wv.w;
    }
    acc.x += __shfl_xor_sync(0xffffffffu, acc.x, 16);
    acc.y += __shfl_xor_sync(0xffffffffu, acc.y, 16);
    acc.z += __shfl_xor_sync(0xffffffffu, acc.z, 16);
    acc.w += __shfl_xor_sync(0xffffffffu, acc.w, 16);
    return acc;
}

// bmm epilogue: store fp32 h, bf16 pack (att2|h), and s1. acc valid half==0.
__device__ __forceinline__ void bmm_epilogue(int wid, int lane, int half, int sub,
                                             float4 acc,
                                             const float* __restrict__ att,
                                             float* __restrict__ hbuf,
                                             uint4* __restrict__ pack,
                                             float* __restrict__ s1buf) {
    if (half == 0) {
        ((float4*)hbuf)[wid * 16 + sub] = acc;
        uint2* pk2 = (uint2*)pack;
        float4 av2 = ((const float4*)(att + (size_t)wid * 2 * DD + DD))[sub];
        pk2[(size_t)wid * 32 + sub]      = to_bf16x4(av2);
        pk2[(size_t)wid * 32 + 16 + sub] = to_bf16x4(acc);
    }
    float4 av = ((const float4*)(att + (size_t)wid * 2 * DD))[sub];
    float part = acc.x * av.x + acc.y * av.y + acc.z * av.z + acc.w * av.w;
    part += __shfl_xor_sync(0xffffffffu, part, 8);
    part += __shfl_xor_sync(0xffffffffu, part, 4);
    part += __shfl_xor_sync(0xffffffffu, part, 2);
    part += __shfl_xor_sync(0xffffffffu, part, 1);
    if (lane == 0) s1buf[wid] = part;
}

// ---------------- quarter-warp segment-softmax aggregation (bf16 pack) ----------------
__device__ __forceinline__ void edge_agg(
    int beg, int end, int j, int quarter, int q,
    const uint4* __restrict__ pack, const float* __restrict__ hbuf,
    const float* __restrict__ s1buf,
    float4& acc0, float4& acc1)
{
    float4 hj0 = ((const float4*)hbuf)[j * 16 + 2 * q];
    float4 hj1 = ((const float4*)hbuf)[j * 16 + 2 * q + 1];
    float s = 0.f;
    acc0 = make_float4(0.f, 0.f, 0.f, 0.f);
    acc1 = make_float4(0.f, 0.f, 0.f, 0.f);
#pragma unroll 2
    for (int base = beg; base < end; base += 4) {
        int p = base + quarter;
        bool active = (p < end);
        int r = active ? g_srow[p] : 0;
        uint4 a4 = pack[(size_t)r * 16 + q];       // att2 bf16 cols 8q..8q+8
        uint4 h4 = pack[(size_t)r * 16 + 8 + q];   // h    bf16 cols 8q..8q+8
        float2 f0 = bf2f(a4.x), f1 = bf2f(a4.y), f2 = bf2f(a4.z), f3 = bf2f(a4.w);
        float part = hj0.x * f0.x + hj0.y * f0.y + hj0.z * f1.x + hj0.w * f1.y
                   + hj1.x * f2.x + hj1.y * f2.y + hj1.z * f3.x + hj1.w * f3.y;
        part += __shfl_xor_sync(0xffffffffu, part, 4);
        part += __shfl_xor_sync(0xffffffffu, part, 2);
        part += __shfl_xor_sync(0xffffffffu, part, 1);
        float sc = s1buf[r] + part;
        sc = (sc >= 0.f) ? sc : 0.2f * sc;   // leaky_relu(0.2)
        sc = fminf(sc, 60.f);                // paranoia clamp (never binds)
        if (!active) sc = -1e30f;
        float wv = __expf(sc);               // softmax w/o max-shift: scores ~N(0,1)
        s += wv;
        float2 g0 = bf2f(h4.x), g1 = bf2f(h4.y), g2 = bf2f(h4.z), g3 = bf2f(h4.w);
        acc0.x += wv * g0.x; acc0.y += wv * g0.y; acc0.z += wv * g1.x; acc0.w += wv * g1.y;
        acc1.x += wv * g2.x; acc1.y += wv * g2.y; acc1.z += wv * g3.x; acc1.w += wv * g3.y;
    }
#pragma unroll
    for (int o = 8; o <= 16; o <<= 1) {
        acc0.x += __shfl_xor_sync(0xffffffffu, acc0.x, o);
        acc0.y += __shfl_xor_sync(0xffffffffu, acc0.y, o);
        acc0.z += __shfl_xor_sync(0xffffffffu, acc0.z, o);
        acc0.w += __shfl_xor_sync(0xffffffffu, acc0.w, o);
        acc1.x += __shfl_xor_sync(0xffffffffu, acc1.x, o);
        acc1.y += __shfl_xor_sync(0xffffffffu, acc1.y, o);
        acc1.z += __shfl_xor_sync(0xffffffffu, acc1.z, o);
        acc1.w += __shfl_xor_sync(0xffffffffu, acc1.w, o);
        s += __shfl_xor_sync(0xffffffffu, s, o);
    }
    float inv = 1.f / s;
    acc0.x *= inv; acc0.y *= inv; acc0.z *= inv; acc0.w *= inv;
    acc1.x *= inv; acc1.y *= inv; acc1.z *= inv; acc1.w *= inv;
}

// ---------------- layer-0 bmm (all nodes) ----------------
__global__ void __launch_bounds__(256) k_bmm0(const float* __restrict__ x,
                                              const float* __restrict__ w,
                                              const float* __restrict__ att) {
    __shared__ float shx[8][64];
    int wid  = (blockIdx.x * blockDim.x + threadIdx.x) >> 5;
    int wl   = threadIdx.x >> 5;
    int lane = threadIdx.x & 31;
    int half = lane >> 4;
    int sub  = lane & 15;
    if (wid >= NN) return;

    float2 xv = ((const float2*)(x + (size_t)wid * DD))[lane];
    shx[wl][2 * lane]     = xv.x;
    shx[wl][2 * lane + 1] = xv.y;
    __syncwarp();

    const float4* wn4 = (const float4*)(w + (size_t)wid * DD * DD);
    float4 acc = bmm_body(wn4, shx[wl], half, sub);
    bmm_epilogue(wid, lane, half, sub, acc, att, g_h, g_pack, g_s1);
}

// ---------------- edge0 chunk: agg + bias + relu -> g_x1 ----------------
__global__ void __launch_bounds__(256) k_edge0(int nbase,
                                               const float* __restrict__ b0) {
    int j    = nbase + ((blockIdx.x * blockDim.x + threadIdx.x) >> 5);
    int lane = threadIdx.x & 31;
    int quarter = lane >> 3;
    int q    = lane & 7;
    if (j >= nbase + CHN) return;

    int beg = g_off[j], end = g_off[j + 1];
    float4 r0, r1;
    if (beg == end) {
        r0 = make_float4(0.f, 0.f, 0.f, 0.f);
        r1 = r0;
    } else {
        edge_agg(beg, end, j, quarter, q, g_pack, g_h, g_s1, r0, r1);
    }
    const float4* bb = (const float4*)b0;
    float4 bv0 = bb[2 * q], bv1 = bb[2 * q + 1];
    r0.x = fmaxf(r0.x + bv0.x, 0.f); r0.y = fmaxf(r0.y + bv0.y, 0.f);
    r0.z = fmaxf(r0.z + bv0.z, 0.f); r0.w = fmaxf(r0.w + bv0.w, 0.f);
    r1.x = fmaxf(r1.x + bv1.x, 0.f); r1.y = fmaxf(r1.y + bv1.y, 0.f);
    r1.z = fmaxf(r1.z + bv1.z, 0.f); r1.w = fmaxf(r1.w + bv1.w, 0.f);
    if (quarter == 0) {
        ((float4*)g_x1)[j * 16 + 2 * q]     = r0;
        ((float4*)g_x1)[j * 16 + 2 * q + 1] = r1;
    }
}

// ---------------- bmm1 chunk: g_x1 -> g_h2, g_pack2, g_s1b ----------------
__global__ void __launch_bounds__(256) k_bmm1(int nbase,
                                              const float* __restrict__ w1,
                                              const float* __restrict__ att1) {
    __shared__ float shx[8][64];
    int wid  = nbase + ((blockIdx.x * blockDim.x + threadIdx.x) >> 5);
    int wl   = threadIdx.x >> 5;
    int lane = threadIdx.x & 31;
    int half = lane >> 4;
    int sub  = lane & 15;
    if (wid >= nbase + CHN) return;

    float2 xv = ((const float2*)(g_x1 + (size_t)wid * DD))[lane];
    shx[wl][2 * lane]     = xv.x;
    shx[wl][2 * lane + 1] = xv.y;
    __syncwarp();

    const float4* wn4 = (const float4*)(w1 + (size_t)wid * DD * DD);
    float4 acc = bmm_body(wn4, shx[wl], half, sub);
    bmm_epilogue(wid, lane, half, sub, acc, att1, g_h2, g_pack2, g_s1b);
}

// ---------------- layer-1 edge aggregation -> output ----------------
__global__ void __launch_bounds__(256) k_edge1(const float* __restrict__ b1,
                                               float* __restrict__ out) {
    int j    = (blockIdx.x * blockDim.x + threadIdx.x) >> 5;
    int lane = threadIdx.x & 31;
    int quarter = lane >> 3;
    int q    = lane & 7;
    if (j >= NN) return;

    int beg = g_off[j], end = g_off[j + 1];
    float4 r0, r1;
    if (beg == end) {
        r0 = make_float4(0.f, 0.f, 0.f, 0.f);
        r1 = r0;
    } else {
        edge_agg(beg, end, j, quarter, q, g_pack2, g_h2, g_s1b, r0, r1);
    }
    const float4* bb = (const float4*)b1;
    float4 bv0 = bb[2 * q], bv1 = bb[2 * q + 1];
    r0.x += bv0.x; r0.y += bv0.y; r0.z += bv0.z; r0.w += bv0.w;
    r1.x += bv1.x; r1.y += bv1.y; r1.z += bv1.z; r1.w += bv1.w;
    if (quarter == 0) {
        ((float4*)out)[j * 16 + 2 * q]     = r0;
        ((float4*)out)[j * 16 + 2 * q + 1] = r1;
    }
}

// ---------------- capture-fork resources ----------------
namespace {
struct Aux {
    cudaStream_t s2 = nullptr;
    cudaEvent_t evA = nullptr, evB = nullptr, evC = nullptr;
    cudaEvent_t evE[NCHUNK] = {};
    bool ok = false;
    Aux() {
        ok = (cudaStreamCreateWithFlags(&s2, cudaStreamNonBlocking) == cudaSuccess) &&
             (cudaEventCreateWithFlags(&evA, cudaEventDisableTiming) == cudaSuccess) &&
             (cudaEventCreateWithFlags(&evB, cudaEventDisableTiming) == cudaSuccess) &&
             (cudaEventCreateWithFlags(&evC, cudaEventDisableTiming) == cudaSuccess);
        for (int i = 0; i < NCHUNK && ok; i++)
            ok = (cudaEventCreateWithFlags(&evE[i], cudaEventDisableTiming) == cudaSuccess);
    }
};
Aux g_aux;
}

// ---------------- launch ----------------
extern "C" void kernel_launch(void* const* d_in, const int* in_sizes, int n_in,
                              void* d_out, int out_size) {
    const float* x    = (const float*)d_in[0];
    const void*  ei   = d_in[1];
    const float* w0   = (const float*)d_in[2];
    const float* att0 = (const float*)d_in[3];
    const float* b0   = (const float*)d_in[4];
    const float* w1   = (const float*)d_in[5];
    const float* att1 = (const float*)d_in[6];
    const float* b1   = (const float*)d_in[7];
    float* out = (float*)d_out;

    const int EB = (EE + 255) / 256;        // 2500
    const int NB = (NN * 32 + 255) / 256;   // 2500 (warp per node)
    const int CB = (CHN * 32 + 255) / 256;  // 313 (chunk kernels)
    const int ZB = (NN + 255) / 256;        // 79

    if (g_aux.ok) {
        // prep on s2 overlaps the DRAM-bound bmm0 on the main stream
        cudaEventRecord(g_aux.evA, 0);
        cudaStreamWaitEvent(g_aux.s2, g_aux.evA, 0);
        k_detect_zero<<<ZB, 256, 0, g_aux.s2>>>(ei);
        k_hist<<<EB, 256, 0, g_aux.s2>>>(ei);
        k_scan<<<1, 1024, 0, g_aux.s2>>>();
        k_bmm0<<<NB, 256>>>(x, w0, att0);
        k_scatter<<<EB, 256, 0, g_aux.s2>>>(ei);
        cudaEventRecord(g_aux.evB, g_aux.s2);
        cudaStreamWaitEvent(0, g_aux.evB, 0);   // edges need g_off/g_srow

        // software pipeline: E_c (L2-gather, main) || B_{c-1} (DRAM stream, s2)
        for (int c = 0; c < NCHUNK; c++) {
            k_edge0<<<CB, 256>>>(c * CHN, b0);
            cudaEventRecord(g_aux.evE[c], 0);
            cudaStreamWaitEvent(g_aux.s2, g_aux.evE[c], 0);
            k_bmm1<<<CB, 256, 0, g_aux.s2>>>(c * CHN, w1, att1);
        }
        cudaEventRecord(g_aux.evC, g_aux.s2);
        cudaStreamWaitEvent(0, g_aux.evC, 0);   // all h2/pack2 ready
        k_edge1<<<NB, 256>>>(b1, out);
    } else {
        k_detect_zero<<<ZB, 256>>>(ei);
        k_hist<<<EB, 256>>>(ei);
        k_scan<<<1, 1024>>>();
        k_bmm0<<<NB, 256>>>(x, w0, att0);
        k_scatter<<<EB, 256>>>(ei);
        for (int c = 0; c < NCHUNK; c++) {
            k_edge0<<<CB, 256>>>(c * CHN, b0);
            k_bmm1<<<CB, 256>>>(c * CHN, w1, att1);
        }
        k_edge1<<<NB, 256>>>(b1, out);
    }
}

// round 8
// speedup vs baseline: 1.1467x; 1.1467x over previous
#include <cuda_runtime.h>
#include <cuda_bf16.h>
#include <cstdint>

#define NN 20000
#define EE 640000
#define DD 64

// ---------------- device scratch ----------------
__device__ float g_h[NN * DD];       // layer-0 features fp32 (dest-side reads)
__device__ float g_h2[NN * DD];      // layer-1 features fp32
__device__ uint4 g_pack[NN * 16];    // per node: 128B att2 bf16 | 128B h bf16
__device__ uint4 g_pack2[NN * 16];   // same for layer 1
__device__ float g_s1[NN];
__device__ float g_s1b[NN];
__device__ int   g_srow[EE];         // source rows sorted by destination
__device__ int   g_cnt[NN];
__device__ int   g_off[NN + 1];
__device__ int   g_cur[NN];
__device__ int   g_is64;

// ---------------- preprocessing ----------------
__global__ void k_detect_zero(const void* ei) {
    int t = blockIdx.x * blockDim.x + threadIdx.x;
    if (t < NN) g_cnt[t] = 0;
    if (t == 0) {
        // int32 buffer read as int64 pairs two indices: hi word nonzero w.h.p.
        const long long* p = (const long long*)ei;
        int ok = 1;
        for (int k = 0; k < 64; k++) {
            long long v = p[k];
            if (v < 0 || v >= NN) { ok = 0; break; }
        }
        g_is64 = ok;
    }
}

__global__ void k_hist(const void* ei) {
    int e = blockIdx.x * blockDim.x + threadIdx.x;
    if (e >= EE) return;
    int c;
    if (g_is64) c = (int)((const long long*)ei)[EE + e];
    else        c = ((const int*)ei)[EE + e];
    atomicAdd(&g_cnt[c], 1);
}

__global__ void k_scan() {
    __shared__ int sh[1024];
    int t = threadIdx.x;
    const int CH = (NN + 1023) / 1024;  // 20
    int base = t * CH;
    int s = 0;
#pragma unroll
    for (int i = 0; i < CH; i++) {
        int idx = base + i;
        if (idx < NN) s += g_cnt[idx];
    }
    sh[t] = s;
    __syncthreads();
    for (int off = 1; off < 1024; off <<= 1) {
        int v = (t >= off) ? sh[t - off] : 0;
        __syncthreads();
        sh[t] += v;
        __syncthreads();
    }
    int run = sh[t] - s;
    for (int i = 0; i < CH; i++) {
        int idx = base + i;
        if (idx < NN) {
            g_off[idx] = run;
            g_cur[idx] = run;
            run += g_cnt[idx];
        }
    }
    if (t == 1023) g_off[NN] = sh[1023];
}

__global__ void k_scatter(const void* ei) {
    int e = blockIdx.x * blockDim.x + threadIdx.x;
    if (e >= EE) return;
    int r, c;
    if (g_is64) {
        const long long* p = (const long long*)ei;
        r = (int)p[e];
        c = (int)p[EE + e];
    } else {
        const int* p = (const int*)ei;
        r = p[e];
        c = p[EE + e];
    }
    int pos = atomicAdd(&g_cur[c], 1);
    g_srow[pos] = r;
}

// ---------------- helpers ----------------
__device__ __forceinline__ uint2 to_bf16x4(float4 v) {
    __nv_bfloat162 p0 = __float22bfloat162_rn(make_float2(v.x, v.y));
    __nv_bfloat162 p1 = __float22bfloat162_rn(make_float2(v.z, v.w));
    uint2 u;
    u.x = *reinterpret_cast<unsigned*>(&p0);
    u.y = *reinterpret_cast<unsigned*>(&p1);
    return u;
}
__device__ __forceinline__ float2 bf2f(unsigned u) {
    return __bfloat1622float2(*reinterpret_cast<__nv_bfloat162*>(&u));
}

// bmm body: out cols 4sub.. for this node (valid in half==0 lanes).
// w loads are EVICT-FIRST (__ldcs): the 655MB read-once stream must not
// displace the ~15MB pack/h working set that the edge phases gather from.
__device__ __forceinline__ float4 bmm_body(const float4* __restrict__ wn4,
                                           const float* xs, int half, int sub) {
    float4 acc = make_float4(0.f, 0.f, 0.f, 0.f);
#pragma unroll
    for (int i = 0; i < 32; i++) {
        int r = half * 32 + i;
        float  xd = xs[r];
        float4 wv = __ldcs(&wn4[r * 16 + sub]);
        acc.x += xd * wv.x;
        acc.y += xd * wv.y;
        acc.z += xd * wv.z;
        acc.w += xd * wv.w;
    }
    acc.x += __shfl_xor_sync(0xffffffffu, acc.x, 16);
    acc.y += __shfl_xor_sync(0xffffffffu, acc.y, 16);
    acc.z += __shfl_xor_sync(0xffffffffu, acc.z, 16);
    acc.w += __shfl_xor_sync(0xffffffffu, acc.w, 16);
    return acc;
}

// bmm epilogue: store fp32 h, bf16 pack (att2|h), and s1. acc valid half==0.
__device__ __forceinline__ void bmm_epilogue(int wid, int lane, int half, int sub,
                                             float4 acc,
                                             const float* __restrict__ att,
                                             float* __restrict__ hbuf,
                                             uint4* __restrict__ pack,
                                             float* __restrict__ s1buf) {
    if (half == 0) {
        ((float4*)hbuf)[wid * 16 + sub] = acc;
        uint2* pk2 = (uint2*)pack;
        float4 av2 = ((const float4*)(att + (size_t)wid * 2 * DD + DD))[sub];
        pk2[(size_t)wid * 32 + sub]      = to_bf16x4(av2);
        pk2[(size_t)wid * 32 + 16 + sub] = to_bf16x4(acc);
    }
    float4 av = ((const float4*)(att + (size_t)wid * 2 * DD))[sub];
    float part = acc.x * av.x + acc.y * av.y + acc.z * av.z + acc.w * av.w;
    part += __shfl_xor_sync(0xffffffffu, part, 8);
    part += __shfl_xor_sync(0xffffffffu, part, 4);
    part += __shfl_xor_sync(0xffffffffu, part, 2);
    part += __shfl_xor_sync(0xffffffffu, part, 1);
    if (lane == 0) s1buf[wid] = part;
}

// ---------------- quarter-warp segment-softmax aggregation (bf16 pack) ----------------
// 4 edges/iter; 8 lanes/edge; lane q covers feature cols [8q, 8q+8).
__device__ __forceinline__ void edge_agg(
    int beg, int end, int j, int quarter, int q,
    const uint4* __restrict__ pack, const float* __restrict__ hbuf,
    const float* __restrict__ s1buf,
    float4& acc0, float4& acc1)
{
    float4 hj0 = ((const float4*)hbuf)[j * 16 + 2 * q];
    float4 hj1 = ((const float4*)hbuf)[j * 16 + 2 * q + 1];
    float s = 0.f;
    acc0 = make_float4(0.f, 0.f, 0.f, 0.f);
    acc1 = make_float4(0.f, 0.f, 0.f, 0.f);
#pragma unroll 2
    for (int base = beg; base < end; base += 4) {
        int p = base + quarter;
        bool active = (p < end);
        int r = active ? g_srow[p] : 0;
        uint4 a4 = pack[(size_t)r * 16 + q];       // att2 bf16 cols 8q..8q+8
        uint4 h4 = pack[(size_t)r * 16 + 8 + q];   // h    bf16 cols 8q..8q+8
        float2 f0 = bf2f(a4.x), f1 = bf2f(a4.y), f2 = bf2f(a4.z), f3 = bf2f(a4.w);
        float part = hj0.x * f0.x + hj0.y * f0.y + hj0.z * f1.x + hj0.w * f1.y
                   + hj1.x * f2.x + hj1.y * f2.y + hj1.z * f3.x + hj1.w * f3.y;
        part += __shfl_xor_sync(0xffffffffu, part, 4);
        part += __shfl_xor_sync(0xffffffffu, part, 2);
        part += __shfl_xor_sync(0xffffffffu, part, 1);
        float sc = s1buf[r] + part;
        sc = (sc >= 0.f) ? sc : 0.2f * sc;   // leaky_relu(0.2)
        sc = fminf(sc, 60.f);                // paranoia clamp (never binds)
        if (!active) sc = -1e30f;
        float wv = __expf(sc);               // softmax w/o max-shift: scores ~N(0,1)
        s += wv;
        float2 g0 = bf2f(h4.x), g1 = bf2f(h4.y), g2 = bf2f(h4.z), g3 = bf2f(h4.w);
        acc0.x += wv * g0.x; acc0.y += wv * g0.y; acc0.z += wv * g1.x; acc0.w += wv * g1.y;
        acc1.x += wv * g2.x; acc1.y += wv * g2.y; acc1.z += wv * g3.x; acc1.w += wv * g3.y;
    }
#pragma unroll
    for (int o = 8; o <= 16; o <<= 1) {
        acc0.x += __shfl_xor_sync(0xffffffffu, acc0.x, o);
        acc0.y += __shfl_xor_sync(0xffffffffu, acc0.y, o);
        acc0.z += __shfl_xor_sync(0xffffffffu, acc0.z, o);
        acc0.w += __shfl_xor_sync(0xffffffffu, acc0.w, o);
        acc1.x += __shfl_xor_sync(0xffffffffu, acc1.x, o);
        acc1.y += __shfl_xor_sync(0xffffffffu, acc1.y, o);
        acc1.z += __shfl_xor_sync(0xffffffffu, acc1.z, o);
        acc1.w += __shfl_xor_sync(0xffffffffu, acc1.w, o);
        s += __shfl_xor_sync(0xffffffffu, s, o);
    }
    float inv = 1.f / s;
    acc0.x *= inv; acc0.y *= inv; acc0.z *= inv; acc0.w *= inv;
    acc1.x *= inv; acc1.y *= inv; acc1.z *= inv; acc1.w *= inv;
}

// ---------------- layer-0 bmm ----------------
__global__ void __launch_bounds__(256) k_bmm0(const float* __restrict__ x,
                                              const float* __restrict__ w,
                                              const float* __restrict__ att) {
    __shared__ float shx[8][64];
    int wid  = (blockIdx.x * blockDim.x + threadIdx.x) >> 5;
    int wl   = threadIdx.x >> 5;
    int lane = threadIdx.x & 31;
    int half = lane >> 4;
    int sub  = lane & 15;
    if (wid >= NN) return;

    float2 xv = ((const float2*)(x + (size_t)wid * DD))[lane];
    shx[wl][2 * lane]     = xv.x;
    shx[wl][2 * lane + 1] = xv.y;
    __syncwarp();

    const float4* wn4 = (const float4*)(w + (size_t)wid * DD * DD);
    float4 acc = bmm_body(wn4, shx[wl], half, sub);
    bmm_epilogue(wid, lane, half, sub, acc, att, g_h, g_pack, g_s1);
}

// ---------------- fused: edge0 aggregation + relu + layer-1 bmm ----------------
__global__ void __launch_bounds__(256) k_fused(const float* __restrict__ b0,
                                               const float* __restrict__ w1,
                                               const float* __restrict__ att1) {
    __shared__ float shx[8][64];
    int j    = (blockIdx.x * blockDim.x + threadIdx.x) >> 5;
    int wl   = threadIdx.x >> 5;
    int lane = threadIdx.x & 31;
    int half = lane >> 4;
    int sub  = lane & 15;
    int quarter = lane >> 3;
    int q    = lane & 7;
    if (j >= NN) return;

    int beg = g_off[j], end = g_off[j + 1];
    float4 r0, r1;
    if (beg == end) {
        r0 = make_float4(0.f, 0.f, 0.f, 0.f);
        r1 = r0;
    } else {
        edge_agg(beg, end, j, quarter, q, g_pack, g_h, g_s1, r0, r1);
    }
    const float4* bb = (const float4*)b0;
    float4 bv0 = bb[2 * q], bv1 = bb[2 * q + 1];
    r0.x = fmaxf(r0.x + bv0.x, 0.f); r0.y = fmaxf(r0.y + bv0.y, 0.f);
    r0.z = fmaxf(r0.z + bv0.z, 0.f); r0.w = fmaxf(r0.w + bv0.w, 0.f);
    r1.x = fmaxf(r1.x + bv1.x, 0.f); r1.y = fmaxf(r1.y + bv1.y, 0.f);
    r1.z = fmaxf(r1.z + bv1.z, 0.f); r1.w = fmaxf(r1.w + bv1.w, 0.f);

    if (quarter == 0) {
        ((float4*)shx[wl])[2 * q]     = r0;
        ((float4*)shx[wl])[2 * q + 1] = r1;
    }
    __syncwarp();

    const float4* wn4 = (const float4*)(w1 + (size_t)j * DD * DD);
    float4 acc = bmm_body(wn4, shx[wl], half, sub);
    bmm_epilogue(j, lane, half, sub, acc, att1, g_h2, g_pack2, g_s1b);
}

// ---------------- layer-1 edge aggregation -> output ----------------
__global__ void __launch_bounds__(256) k_edge1(const float* __restrict__ b1,
                                               float* __restrict__ out) {
    int j    = (blockIdx.x * blockDim.x + threadIdx.x) >> 5;
    int lane = threadIdx.x & 31;
    int quarter = lane >> 3;
    int q    = lane & 7;
    if (j >= NN) return;

    int beg = g_off[j], end = g_off[j + 1];
    float4 r0, r1;
    if (beg == end) {
        r0 = make_float4(0.f, 0.f, 0.f, 0.f);
        r1 = r0;
    } else {
        edge_agg(beg, end, j, quarter, q, g_pack2, g_h2, g_s1b, r0, r1);
    }
    const float4* bb = (const float4*)b1;
    float4 bv0 = bb[2 * q], bv1 = bb[2 * q + 1];
    r0.x += bv0.x; r0.y += bv0.y; r0.z += bv0.z; r0.w += bv0.w;
    r1.x += bv1.x; r1.y += bv1.y; r1.z += bv1.z; r1.w += bv1.w;
    if (quarter == 0) {
        ((float4*)out)[j * 16 + 2 * q]     = r0;
        ((float4*)out)[j * 16 + 2 * q + 1] = r1;
    }
}

// ---------------- capture-fork resources ----------------
namespace {
struct Aux {
    cudaStream_t s2 = nullptr;
    cudaEvent_t evA = nullptr, evB = nullptr;
    bool ok = false;
    Aux() {
        ok = (cudaStreamCreateWithFlags(&s2, cudaStreamNonBlocking) == cudaSuccess) &&
             (cudaEventCreateWithFlags(&evA, cudaEventDisableTiming) == cudaSuccess) &&
             (cudaEventCreateWithFlags(&evB, cudaEventDisableTiming) == cudaSuccess);
    }
};
Aux g_aux;
}

// ---------------- launch ----------------
extern "C" void kernel_launch(void* const* d_in, const int* in_sizes, int n_in,
                              void* d_out, int out_size) {
    const float* x    = (const float*)d_in[0];
    const void*  ei   = d_in[1];
    const float* w0   = (const float*)d_in[2];
    const float* att0 = (const float*)d_in[3];
    const float* b0   = (const float*)d_in[4];
    const float* w1   = (const float*)d_in[5];
    const float* att1 = (const float*)d_in[6];
    const float* b1   = (const float*)d_in[7];
    float* out = (float*)d_out;

    const int EB = (EE + 255) / 256;       // 2500
    const int NB = (NN * 32 + 255) / 256;  // 2500 (warp per node)
    const int ZB = (NN + 255) / 256;       // 79

    if (g_aux.ok) {
        // prep on s2 overlaps DRAM-bound bmm0.
        // order: detect(1) hist(2) scan(3) bmm0(4) scatter(5) fused(6)
        // -> ncu -s 5 -c 1 captures k_fused.
        cudaEventRecord(g_aux.evA, 0);
        cudaStreamWaitEvent(g_aux.s2, g_aux.evA, 0);
        k_detect_zero<<<ZB, 256, 0, g_aux.s2>>>(ei);
        k_hist<<<EB, 256, 0, g_aux.s2>>>(ei);
        k_scan<<<1, 1024, 0, g_aux.s2>>>();
        k_bmm0<<<NB, 256>>>(x, w0, att0);
        k_scatter<<<EB, 256, 0, g_aux.s2>>>(ei);
        cudaEventRecord(g_aux.evB, g_aux.s2);
        cudaStreamWaitEvent(0, g_aux.evB, 0);
    } else {
        k_detect_zero<<<ZB, 256>>>(ei);
        k_hist<<<EB, 256>>>(ei);
        k_scan<<<1, 1024>>>();
        k_bmm0<<<NB, 256>>>(x, w0, att0);
        k_scatter<<<EB, 256>>>(ei);
    }

    k_fused<<<NB, 256>>>(b0, w1, att1);   // edge0 + bmm1 -> g_h2, g_pack2, g_s1b
    k_edge1<<<NB, 256>>>(b1, out);        // edge1 -> d_out
}